// round 1
// baseline (speedup 1.0000x reference)
#include <cuda_runtime.h>
#include <mma.h>
#include <cstdint>
#include <cstddef>

using namespace nvcuda;

#define S_LEN 512
#define BSZ   64
#define IDIM  512
#define HDIM  512
#define NG    2048          // 4*H
#define NBLK_REC 128
#define REC_THREADS 256

// ---- scratch (device globals: allocation-guard safe) ----
__device__ float g_xg[2][S_LEN][BSZ][NG];   // 512 MB: X@W^T + Wb + Rb, per dir/time
__device__ float g_h[2][2][BSZ][HDIM];      // ping-pong h buffers [buf][dir][b][j]
__device__ unsigned int g_bar_count;
__device__ unsigned int g_bar_gen;

static const size_t Y_ELEMS  = (size_t)S_LEN * 2 * BSZ * HDIM; // 33,554,432
static const size_t YH_OFF_C = Y_ELEMS;
static const size_t YC_OFF_C = Y_ELEMS + (size_t)2 * BSZ * HDIM;

__device__ __forceinline__ float sigmoidf_(float x) { return 1.0f / (1.0f + __expf(-x)); }

// Software grid barrier for the persistent kernel (128 co-resident blocks).
__device__ __forceinline__ void grid_sync() {
    __threadfence();
    __syncthreads();
    if (threadIdx.x == 0) {
        volatile unsigned int* vgen = &g_bar_gen;
        unsigned int gen = *vgen;
        unsigned int arrived = atomicAdd(&g_bar_count, 1u);
        if (arrived == NBLK_REC - 1) {
            g_bar_count = 0u;
            __threadfence();
            atomicExch(&g_bar_gen, gen + 1u);
        } else {
            while (*vgen == gen) { }
        }
        __threadfence();
    }
    __syncthreads();
}

// ============================================================================
// Kernel A: Xg[d][s][b][n] = sum_k X[s][b][k] * W[d][n][k] + Wb[d][n] + Rb[d][n]
// GEMM M=32768 (s*64+b), N=2048, K=512 per direction. wmma tf32 m16n16k8.
// Block tile 64x64, BK=32, 8 warps: 4(m) x 2(n), each warp 16x32 (2 tiles).
// ============================================================================
__global__ void __launch_bounds__(256)
xg_gemm(const float* __restrict__ X, const float* __restrict__ W,
        const float* __restrict__ Bias)
{
    const int d  = blockIdx.z;
    const int n0 = blockIdx.x * 64;
    const int m0 = blockIdx.y * 64;

    __shared__ float As[64][40];
    __shared__ float Bs[64][40];
    __shared__ float Cs[64][72];

    const int tid = threadIdx.x;
    const int w   = tid >> 5;
    const int wm  = w >> 1;     // 0..3
    const int wn  = w & 1;      // 0..1

    wmma::fragment<wmma::accumulator, 16, 16, 8, float> acc0, acc1;
    wmma::fill_fragment(acc0, 0.0f);
    wmma::fill_fragment(acc1, 0.0f);

    const float* Wd = W + (size_t)d * NG * IDIM;

    for (int k0 = 0; k0 < IDIM; k0 += 32) {
        // load A tile (64x32) and B tile (64x32), both K-contiguous
        for (int i = tid; i < 512; i += 256) {       // 512 float4 each
            int r  = i >> 3;
            int kk = (i & 7) << 2;
            float4 va = *(const float4*)(X  + (size_t)(m0 + r) * IDIM + k0 + kk);
            *(float4*)&As[r][kk] = va;
            float4 vb = *(const float4*)(Wd + (size_t)(n0 + r) * IDIM + k0 + kk);
            *(float4*)&Bs[r][kk] = vb;
        }
        __syncthreads();

        #pragma unroll
        for (int kk = 0; kk < 32; kk += 8) {
            wmma::fragment<wmma::matrix_a, 16, 16, 8, wmma::precision::tf32, wmma::row_major> af;
            wmma::load_matrix_sync(af, &As[wm * 16][kk], 40);
            #pragma unroll
            for (int e = 0; e < af.num_elements; e++) af.x[e] = wmma::__float_to_tf32(af.x[e]);

            wmma::fragment<wmma::matrix_b, 16, 16, 8, wmma::precision::tf32, wmma::col_major> bf0, bf1;
            wmma::load_matrix_sync(bf0, &Bs[wn * 32][kk], 40);
            wmma::load_matrix_sync(bf1, &Bs[wn * 32 + 16][kk], 40);
            #pragma unroll
            for (int e = 0; e < bf0.num_elements; e++) {
                bf0.x[e] = wmma::__float_to_tf32(bf0.x[e]);
                bf1.x[e] = wmma::__float_to_tf32(bf1.x[e]);
            }
            wmma::mma_sync(acc0, af, bf0, acc0);
            wmma::mma_sync(acc1, af, bf1, acc1);
        }
        __syncthreads();
    }

    wmma::store_matrix_sync(&Cs[wm * 16][wn * 32],      acc0, 72, wmma::mem_row_major);
    wmma::store_matrix_sync(&Cs[wm * 16][wn * 32 + 16], acc1, 72, wmma::mem_row_major);
    __syncthreads();

    const float* bd = Bias + (size_t)d * 4096;      // [0,2048)=Wb, [2048,4096)=Rb
    float* xgd = &g_xg[d][0][0][0];
    for (int i = tid; i < 4096; i += 256) {
        int r = i >> 6, c = i & 63;
        int n = n0 + c;
        xgd[(size_t)(m0 + r) * NG + n] = Cs[r][c] + bd[n] + bd[2048 + n];
    }
}

// ============================================================================
// Kernel B: persistent bidirectional recurrence.
// 128 blocks: dir = blk/64, j-chunk of 8 hidden cols = 32 gate rows of R.
// Per step: stage h (64x512) to smem, wmma 64x32 GEMM vs cached R slice,
// fused peephole-LSTM cell in registers, write h_next (ping-pong) + Y,
// one grid barrier per step.
// ============================================================================
__global__ void __launch_bounds__(REC_THREADS, 1)
lstm_rec(const float* __restrict__ R, const int* __restrict__ seqlen,
         const float* __restrict__ h0g, const float* __restrict__ c0g,
         const float* __restrict__ P, float* __restrict__ out)
{
    extern __shared__ __align__(128) float sm[];
    float* h_s = sm;                         // 64 x 520
    float* R_s = sm + 64 * 520;              // 32 x 520
    float* Cs  = sm + 64 * 520 + 32 * 520;   // 64 x 40

    const int tid = threadIdx.x;
    const int d   = blockIdx.x >> 6;
    const int j0  = (blockIdx.x & 63) << 3;

    // cache this block's 32 R rows (gate g, col j0+jj -> row g*H + j0 + jj), once
    const float* Rd = R + (size_t)d * NG * HDIM;
    for (int i = tid; i < 4096; i += REC_THREADS) {       // 32*512/4 float4
        int c = i >> 7, k = (i & 127) << 2;
        int rrow = (c >> 3) * HDIM + j0 + (c & 7);
        *(float4*)&R_s[c * 520 + k] = *(const float4*)(Rd + (size_t)rrow * HDIM + k);
    }
    // init ping buffer 0 with initial_h for this chunk
    for (int i = tid; i < 512; i += REC_THREADS) {
        int b = i >> 3, jj = i & 7;
        g_h[0][d][b][j0 + jj] = h0g[(size_t)(d * BSZ + b) * HDIM + j0 + jj];
    }

    // per-thread cell state: pairs (b0, jj) and (b1, jj)
    const int jj = tid & 7;
    const int b0 = tid >> 3;       // 0..31
    const int b1 = b0 + 32;
    const int jg = j0 + jj;
    const float Pi = P[(size_t)d * 1536 + jg];
    const float Pf = P[(size_t)d * 1536 + 512 + jg];
    const float Po = P[(size_t)d * 1536 + 1024 + jg];
    const int sl0 = seqlen[b0], sl1 = seqlen[b1];
    const float h00 = h0g[(size_t)(d * BSZ + b0) * HDIM + jg];
    const float h01 = h0g[(size_t)(d * BSZ + b1) * HDIM + jg];
    const float c00 = c0g[(size_t)(d * BSZ + b0) * HDIM + jg];
    const float c01 = c0g[(size_t)(d * BSZ + b1) * HDIM + jg];
    float cr0 = c00, cr1 = c01;

    const int w = tid >> 5, wm = w >> 1, wn = w & 1;

    grid_sync();   // all initial_h writes visible

    for (int step = 0; step < S_LEN; step++) {
        const int cur = step & 1, nxt = cur ^ 1;

        // stage full h into shared
        const float* hsrc = &g_h[cur][d][0][0];
        for (int i = tid; i < 8192; i += REC_THREADS) {   // 64*512/4 float4
            int b = i >> 7, k = (i & 127) << 2;
            *(float4*)&h_s[b * 520 + k] = *(const float4*)(hsrc + (size_t)b * HDIM + k);
        }
        __syncthreads();

        // C(64x32) = h(64x512) @ R_slice^T; warp (wm,wn) owns 16x16 tile
        wmma::fragment<wmma::accumulator, 16, 16, 8, float> acc;
        wmma::fill_fragment(acc, 0.0f);
        const float* ha = &h_s[wm * 16 * 520];
        const float* rb = &R_s[wn * 16 * 520];
        #pragma unroll 4
        for (int k = 0; k < HDIM; k += 8) {
            wmma::fragment<wmma::matrix_a, 16, 16, 8, wmma::precision::tf32, wmma::row_major> af;
            wmma::fragment<wmma::matrix_b, 16, 16, 8, wmma::precision::tf32, wmma::col_major> bf;
            wmma::load_matrix_sync(af, ha + k, 520);
            wmma::load_matrix_sync(bf, rb + k, 520);
            #pragma unroll
            for (int e = 0; e < af.num_elements; e++) af.x[e] = wmma::__float_to_tf32(af.x[e]);
            #pragma unroll
            for (int e = 0; e < bf.num_elements; e++) bf.x[e] = wmma::__float_to_tf32(bf.x[e]);
            wmma::mma_sync(acc, af, bf, acc);
        }
        wmma::store_matrix_sync(&Cs[(wm * 16) * 40 + wn * 16], acc, 40, wmma::mem_row_major);
        __syncthreads();

        const int t = (d == 0) ? step : (S_LEN - 1 - step);
        const float* xg = &g_xg[d][t][0][0];

        // cell update, pair 0
        {
            const float* xb = xg + (size_t)b0 * NG;
            float gi = Cs[b0 * 40 + jj]      + xb[jg];
            float go = Cs[b0 * 40 + 8 + jj]  + xb[512 + jg];
            float gf = Cs[b0 * 40 + 16 + jj] + xb[1024 + jg];
            float gc = Cs[b0 * 40 + 24 + jj] + xb[1536 + jg];
            float it = sigmoidf_(gi + Pi * cr0);
            float ft = sigmoidf_(gf + Pf * cr0);
            float cn = ft * cr0 + it * tanhf(gc);
            float ot = sigmoidf_(go + Po * cn);
            float hn = ot * tanhf(cn);
            if (t >= sl0) { hn = h00; cn = c00; }
            cr0 = cn;
            g_h[nxt][d][b0][jg] = hn;
            out[((size_t)(t * 2 + d) * BSZ + b0) * HDIM + jg] = hn;
            if (step == S_LEN - 1) {
                out[YH_OFF_C + (size_t)(d * BSZ + b0) * HDIM + jg] = hn;
                out[YC_OFF_C + (size_t)(d * BSZ + b0) * HDIM + jg] = cn;
            }
        }
        // cell update, pair 1
        {
            const float* xb = xg + (size_t)b1 * NG;
            float gi = Cs[b1 * 40 + jj]      + xb[jg];
            float go = Cs[b1 * 40 + 8 + jj]  + xb[512 + jg];
            float gf = Cs[b1 * 40 + 16 + jj] + xb[1024 + jg];
            float gc = Cs[b1 * 40 + 24 + jj] + xb[1536 + jg];
            float it = sigmoidf_(gi + Pi * cr1);
            float ft = sigmoidf_(gf + Pf * cr1);
            float cn = ft * cr1 + it * tanhf(gc);
            float ot = sigmoidf_(go + Po * cn);
            float hn = ot * tanhf(cn);
            if (t >= sl1) { hn = h01; cn = c01; }
            cr1 = cn;
            g_h[nxt][d][b1][jg] = hn;
            out[((size_t)(t * 2 + d) * BSZ + b1) * HDIM + jg] = hn;
            if (step == S_LEN - 1) {
                out[YH_OFF_C + (size_t)(d * BSZ + b1) * HDIM + jg] = hn;
                out[YC_OFF_C + (size_t)(d * BSZ + b1) * HDIM + jg] = cn;
            }
        }

        grid_sync();   // h_next fully written before anyone reads it
    }
}

// ============================================================================
extern "C" void kernel_launch(void* const* d_in, const int* in_sizes, int n_in,
                              void* d_out, int out_size)
{
    const float* X    = (const float*)d_in[0];  // (512, 64, 512)
    const float* W    = (const float*)d_in[1];  // (2, 2048, 512)
    const float* R    = (const float*)d_in[2];  // (2, 2048, 512)
    const float* Bias = (const float*)d_in[3];  // (2, 4096)
    const int*   seq  = (const int*)  d_in[4];  // (64,)
    const float* h0   = (const float*)d_in[5];  // (2, 64, 512)
    const float* c0   = (const float*)d_in[6];  // (2, 64, 512)
    const float* P    = (const float*)d_in[7];  // (2, 1536)
    float* out = (float*)d_out;

    // Phase 1: input projection (+ both biases folded in)
    dim3 gA(NG / 64, (S_LEN * BSZ) / 64, 2);
    xg_gemm<<<gA, 256>>>(X, W, Bias);

    // Phase 2: persistent recurrence
    const int smem_bytes = (64 * 520 + 32 * 520 + 64 * 40) * (int)sizeof(float); // 209,920
    cudaFuncSetAttribute(lstm_rec, cudaFuncAttributeMaxDynamicSharedMemorySize, smem_bytes);
    lstm_rec<<<NBLK_REC, REC_THREADS, smem_bytes>>>(R, seq, h0, c0, P, out);
}

// round 9
// speedup vs baseline: 1.5371x; 1.5371x over previous
#include <cuda_runtime.h>
#include <mma.h>
#include <cstdint>
#include <cstddef>

using namespace nvcuda;

#define S_LEN 512
#define BSZ   64
#define IDIM  512
#define HDIM  512
#define NG    2048          // 4*H
#define NBLK_REC 128        // 64 per direction
#define REC_THREADS 256

// ---- scratch (device globals: allocation-guard safe) ----
__device__ float g_xg[2][S_LEN][BSZ][NG];   // 512 MB: X@W^T + Wb + Rb, per dir/time
__device__ float g_h[2][2][BSZ][HDIM];      // ping-pong h buffers [buf][dir][b][j]
__device__ unsigned int g_cnt[2][513];      // per-dir step counters; [512]=init. Monotonic, never reset.

static const size_t Y_ELEMS  = (size_t)S_LEN * 2 * BSZ * HDIM; // 33,554,432
static const size_t YH_OFF_C = Y_ELEMS;
static const size_t YC_OFF_C = Y_ELEMS + (size_t)2 * BSZ * HDIM;

#define PART_LD 40          // partials leading dim: 160B = multiple of 16B (wmma-legal)

__device__ __forceinline__ float sigmoidf_(float x) { return 1.0f / (1.0f + __expf(-x)); }

__device__ __forceinline__ unsigned int ld_acq_u32(const unsigned int* p) {
    unsigned int v;
    asm volatile("ld.acquire.gpu.global.u32 %0, [%1];" : "=r"(v) : "l"(p) : "memory");
    return v;
}
__device__ __forceinline__ void red_rel_add(unsigned int* p, unsigned int v) {
    asm volatile("red.release.gpu.global.add.u32 [%0], %1;" :: "l"(p), "r"(v) : "memory");
}

// ============================================================================
// Kernel A: Xg[d][s][b][n] = sum_k X[s][b][k] * W[d][n][k] + Wb[d][n] + Rb[d][n]
// ============================================================================
__global__ void __launch_bounds__(256)
xg_gemm(const float* __restrict__ X, const float* __restrict__ W,
        const float* __restrict__ Bias)
{
    const int d  = blockIdx.z;
    const int n0 = blockIdx.x * 64;
    const int m0 = blockIdx.y * 64;

    __shared__ float As[64][40];
    __shared__ float Bs[64][40];
    __shared__ float Cs[64][72];

    const int tid = threadIdx.x;
    const int w   = tid >> 5;
    const int wm  = w >> 1;
    const int wn  = w & 1;

    wmma::fragment<wmma::accumulator, 16, 16, 8, float> acc0, acc1;
    wmma::fill_fragment(acc0, 0.0f);
    wmma::fill_fragment(acc1, 0.0f);

    const float* Wd = W + (size_t)d * NG * IDIM;

    for (int k0 = 0; k0 < IDIM; k0 += 32) {
        for (int i = tid; i < 512; i += 256) {
            int r  = i >> 3;
            int kk = (i & 7) << 2;
            float4 va = *(const float4*)(X  + (size_t)(m0 + r) * IDIM + k0 + kk);
            *(float4*)&As[r][kk] = va;
            float4 vb = *(const float4*)(Wd + (size_t)(n0 + r) * IDIM + k0 + kk);
            *(float4*)&Bs[r][kk] = vb;
        }
        __syncthreads();

        #pragma unroll
        for (int kk = 0; kk < 32; kk += 8) {
            wmma::fragment<wmma::matrix_a, 16, 16, 8, wmma::precision::tf32, wmma::row_major> af;
            wmma::load_matrix_sync(af, &As[wm * 16][kk], 40);
            #pragma unroll
            for (int e = 0; e < af.num_elements; e++) af.x[e] = wmma::__float_to_tf32(af.x[e]);

            wmma::fragment<wmma::matrix_b, 16, 16, 8, wmma::precision::tf32, wmma::col_major> bf0, bf1;
            wmma::load_matrix_sync(bf0, &Bs[wn * 32][kk], 40);
            wmma::load_matrix_sync(bf1, &Bs[wn * 32 + 16][kk], 40);
            #pragma unroll
            for (int e = 0; e < bf0.num_elements; e++) {
                bf0.x[e] = wmma::__float_to_tf32(bf0.x[e]);
                bf1.x[e] = wmma::__float_to_tf32(bf1.x[e]);
            }
            wmma::mma_sync(acc0, af, bf0, acc0);
            wmma::mma_sync(acc1, af, bf1, acc1);
        }
        __syncthreads();
    }

    wmma::store_matrix_sync(&Cs[wm * 16][wn * 32],      acc0, 72, wmma::mem_row_major);
    wmma::store_matrix_sync(&Cs[wm * 16][wn * 32 + 16], acc1, 72, wmma::mem_row_major);
    __syncthreads();

    const float* bd = Bias + (size_t)d * 4096;
    float* xgd = &g_xg[d][0][0][0];
    for (int i = tid; i < 4096; i += 256) {
        int r = i >> 6, c = i & 63;
        int n = n0 + c;
        xgd[(size_t)(m0 + r) * NG + n] = Cs[r][c] + bd[n] + bd[2048 + n];
    }
}

// ============================================================================
// Kernel B: persistent bidirectional recurrence.
//  - 128 blocks: dir = blk/64, 8 hidden cols each (32 gate rows of R).
//  - R(32x512) converted to tf32 fragments held in REGISTERS (loaded once).
//  - 8 warps = 2(m-half: 32 rows) x 4(k-split: 128 k each).
//  - Pair-chunked h staging (ld.cg + named pair barrier), k-split partials
//    reduced in smem with LEGAL ldm=40 (round-6 bug: ldm=33 was misaligned).
//  - Grid sync: syncthreads + elected red.release / ld.acquire poll.
// ============================================================================
__global__ void __launch_bounds__(REC_THREADS, 1)
lstm_rec(const float* __restrict__ R, const int* __restrict__ seqlen,
         const float* __restrict__ h0g, const float* __restrict__ c0g,
         const float* __restrict__ P, float* __restrict__ out)
{
    extern __shared__ __align__(128) float sm[];
    float* h_s  = sm;                 // 64 x 520 = 33280 floats
    float* ovl  = sm + 64 * 520;      // overlay: R_s (init: 32x520) / partials (loop: 8x32x40)

    const int tid = threadIdx.x;
    const int d   = (int)(blockIdx.x >> 6);
    const int j0  = (int)(blockIdx.x & 63) << 3;

    const int wid = tid >> 5;
    const int wm  = wid & 1;          // m-half: rows wm*32..+32
    const int wk  = wid >> 1;         // k-slice: k in [wk*128, wk*128+128)

    // ---- baseline counter read (MUST precede our init arrive) ----
    const unsigned int base = ld_acq_u32(&g_cnt[d][0]);
    const unsigned int target = base + 64;

    // ---- stage R slice into smem (rows: gate g, col j0+jj -> R row g*H+j0+jj) ----
    const float* Rd = R + (size_t)d * NG * HDIM;
    for (int i = tid; i < 4096; i += REC_THREADS) {       // 32*512/4 float4
        int c = i >> 7, k = (i & 127) << 2;
        int rrow = (c >> 3) * HDIM + j0 + (c & 7);
        *(float4*)&ovl[c * 520 + k] = *(const float4*)(Rd + (size_t)rrow * HDIM + k);
    }
    // init ping buffer 0 with initial_h for this chunk (st.cg: consumers use ld.cg)
    for (int i = tid; i < 512; i += REC_THREADS) {
        int b = i >> 3, jj = i & 7;
        __stcg(&g_h[0][d][b][j0 + jj], h0g[(size_t)(d * BSZ + b) * HDIM + j0 + jj]);
    }
    __syncthreads();

    // ---- load B (R) fragments into registers, tf32-convert once ----
    wmma::fragment<wmma::matrix_b, 16, 16, 8, wmma::precision::tf32, wmma::col_major> bfr[16][2];
    #pragma unroll
    for (int ks = 0; ks < 16; ks++) {
        #pragma unroll
        for (int nh = 0; nh < 2; nh++) {
            wmma::load_matrix_sync(bfr[ks][nh], &ovl[(nh * 16) * 520 + wk * 128 + ks * 8], 520);
            #pragma unroll
            for (int e = 0; e < bfr[ks][nh].num_elements; e++)
                bfr[ks][nh].x[e] = wmma::__float_to_tf32(bfr[ks][nh].x[e]);
        }
    }

    // ---- per-thread cell state ----
    const int jj = tid & 7;
    const int b0 = tid >> 3;       // 0..31
    const int b1 = b0 + 32;
    const int jg = j0 + jj;
    const float Pi = P[(size_t)d * 1536 + jg];
    const float Pf = P[(size_t)d * 1536 + 512 + jg];
    const float Po = P[(size_t)d * 1536 + 1024 + jg];
    const int sl0 = seqlen[b0], sl1 = seqlen[b1];
    const float h00 = h0g[(size_t)(d * BSZ + b0) * HDIM + jg];
    const float h01 = h0g[(size_t)(d * BSZ + b1) * HDIM + jg];
    const float c00 = c0g[(size_t)(d * BSZ + b0) * HDIM + jg];
    const float c01 = c0g[(size_t)(d * BSZ + b1) * HDIM + jg];
    float cr0 = c00, cr1 = c01;

    __syncthreads();                                  // orders bfr reads + g_h[0] writes
    if (tid == 0) red_rel_add(&g_cnt[d][512], 1u);    // init arrive (release)

    const int pair_tid = tid & 63;                    // thread id within 2-warp pair
    float* part = ovl;                                // partials: [8][32][PART_LD]

    for (int step = 0; step < S_LEN; step++) {
        const int cur = step & 1, nxt = cur ^ 1;
        const int t = (d == 0) ? step : (S_LEN - 1 - step);
        const float* xg = &g_xg[d][t][0][0];

        // prefetch xg gate values (DRAM, streaming) — independent of barrier
        float xv0[4], xv1[4];
        #pragma unroll
        for (int g = 0; g < 4; g++) {
            xv0[g] = __ldcs(xg + (size_t)b0 * NG + g * 512 + jg);
            xv1[g] = __ldcs(xg + (size_t)b1 * NG + g * 512 + jg);
        }

        // wait: all 64 blocks of this direction finished producing g_h[cur]
        if (tid == 0) {
            const unsigned int* cp = &g_cnt[d][(step == 0) ? 512 : (step - 1)];
            while (ld_acq_u32(cp) != target) { }
        }
        __syncthreads();

        // stage this pair's 32KB h chunk: rows 0..63, k in [wk*128,+128)
        const float* hsrc = &g_h[cur][d][0][0];
        {
            const int kbase = wk * 128;
            #pragma unroll
            for (int i = pair_tid; i < 2048; i += 64) {     // 2048 float4 per chunk
                int b = i >> 5, kq = (i & 31) << 2;
                float4 v = __ldcg((const float4*)(hsrc + (size_t)b * HDIM + kbase + kq));
                *(float4*)&h_s[b * 520 + kbase + kq] = v;
            }
        }
        asm volatile("bar.sync %0, %1;" :: "r"(wk + 1), "r"(64) : "memory");

        // mma: warp computes partial C[wm*32:+32, 0:32] over k slice [wk*128,+128)
        wmma::fragment<wmma::accumulator, 16, 16, 8, float> acc[2][2];
        #pragma unroll
        for (int mh = 0; mh < 2; mh++)
            #pragma unroll
            for (int nh = 0; nh < 2; nh++)
                wmma::fill_fragment(acc[mh][nh], 0.0f);

        #pragma unroll
        for (int ks = 0; ks < 16; ks++) {
            wmma::fragment<wmma::matrix_a, 16, 16, 8, wmma::precision::tf32, wmma::row_major> af0, af1;
            wmma::load_matrix_sync(af0, &h_s[(wm * 32) * 520      + wk * 128 + ks * 8], 520);
            wmma::load_matrix_sync(af1, &h_s[(wm * 32 + 16) * 520 + wk * 128 + ks * 8], 520);
            #pragma unroll
            for (int e = 0; e < af0.num_elements; e++) {
                af0.x[e] = wmma::__float_to_tf32(af0.x[e]);
                af1.x[e] = wmma::__float_to_tf32(af1.x[e]);
            }
            wmma::mma_sync(acc[0][0], af0, bfr[ks][0], acc[0][0]);
            wmma::mma_sync(acc[0][1], af0, bfr[ks][1], acc[0][1]);
            wmma::mma_sync(acc[1][0], af1, bfr[ks][0], acc[1][0]);
            wmma::mma_sync(acc[1][1], af1, bfr[ks][1], acc[1][1]);
        }

        // store k-split partials: part[wid] is [32][PART_LD]  (ldm=40: 16B-multiple)
        {
            float* pw = part + wid * (32 * PART_LD);
            #pragma unroll
            for (int mh = 0; mh < 2; mh++)
                #pragma unroll
                for (int nh = 0; nh < 2; nh++)
                    wmma::store_matrix_sync(pw + (mh * 16) * PART_LD + nh * 16, acc[mh][nh],
                                            PART_LD, wmma::mem_row_major);
        }
        __syncthreads();

        // reduce 4 k-partials + fused cell update
        {
            const int wmsel0 = b0 >> 5, row0 = b0 & 31;   // 0
            const int wmsel1 = b1 >> 5, row1 = b1 & 31;   // 1
            float gs0[4], gs1[4];
            #pragma unroll
            for (int g = 0; g < 4; g++) {
                const int c = g * 8 + jj;
                float s0 = 0.f, s1 = 0.f;
                #pragma unroll
                for (int kw = 0; kw < 4; kw++) {
                    s0 += part[((kw << 1) | wmsel0) * (32 * PART_LD) + row0 * PART_LD + c];
                    s1 += part[((kw << 1) | wmsel1) * (32 * PART_LD) + row1 * PART_LD + c];
                }
                gs0[g] = s0; gs1[g] = s1;
            }

            // pair 0
            {
                float gi = gs0[0] + xv0[0];
                float go = gs0[1] + xv0[1];
                float gf = gs0[2] + xv0[2];
                float gc = gs0[3] + xv0[3];
                float it = sigmoidf_(gi + Pi * cr0);
                float ft = sigmoidf_(gf + Pf * cr0);
                float cn = ft * cr0 + it * tanhf(gc);
                float ot = sigmoidf_(go + Po * cn);
                float hn = ot * tanhf(cn);
                if (t >= sl0) { hn = h00; cn = c00; }
                cr0 = cn;
                __stcg(&g_h[nxt][d][b0][jg], hn);
                __stcs(out + ((size_t)(t * 2 + d) * BSZ + b0) * HDIM + jg, hn);
                if (step == S_LEN - 1) {
                    out[YH_OFF_C + (size_t)(d * BSZ + b0) * HDIM + jg] = hn;
                    out[YC_OFF_C + (size_t)(d * BSZ + b0) * HDIM + jg] = cn;
                }
            }
            // pair 1
            {
                float gi = gs1[0] + xv1[0];
                float go = gs1[1] + xv1[1];
                float gf = gs1[2] + xv1[2];
                float gc = gs1[3] + xv1[3];
                float it = sigmoidf_(gi + Pi * cr1);
                float ft = sigmoidf_(gf + Pf * cr1);
                float cn = ft * cr1 + it * tanhf(gc);
                float ot = sigmoidf_(go + Po * cn);
                float hn = ot * tanhf(cn);
                if (t >= sl1) { hn = h01; cn = c01; }
                cr1 = cn;
                __stcg(&g_h[nxt][d][b1][jg], hn);
                __stcs(out + ((size_t)(t * 2 + d) * BSZ + b1) * HDIM + jg, hn);
                if (step == S_LEN - 1) {
                    out[YH_OFF_C + (size_t)(d * BSZ + b1) * HDIM + jg] = hn;
                    out[YC_OFF_C + (size_t)(d * BSZ + b1) * HDIM + jg] = cn;
                }
            }
        }

        __syncthreads();                                    // all h writes + partial reads done
        if (tid == 0) red_rel_add(&g_cnt[d][step], 1u);     // arrive (release)
    }
}

// ============================================================================
extern "C" void kernel_launch(void* const* d_in, const int* in_sizes, int n_in,
                              void* d_out, int out_size)
{
    const float* X    = (const float*)d_in[0];  // (512, 64, 512)
    const float* W    = (const float*)d_in[1];  // (2, 2048, 512)
    const float* R    = (const float*)d_in[2];  // (2, 2048, 512)
    const float* Bias = (const float*)d_in[3];  // (2, 4096)
    const int*   seq  = (const int*)  d_in[4];  // (64,)
    const float* h0   = (const float*)d_in[5];  // (2, 64, 512)
    const float* c0   = (const float*)d_in[6];  // (2, 64, 512)
    const float* P    = (const float*)d_in[7];  // (2, 1536)
    float* out = (float*)d_out;

    // Phase 1: input projection (+ both biases folded in)
    dim3 gA(NG / 64, (S_LEN * BSZ) / 64, 2);
    xg_gemm<<<gA, 256>>>(X, W, Bias);

    // Phase 2: persistent recurrence
    const int smem_bytes = (64 * 520 + 32 * 520) * (int)sizeof(float); // 199,680
    cudaFuncSetAttribute(lstm_rec, cudaFuncAttributeMaxDynamicSharedMemorySize, smem_bytes);
    lstm_rec<<<NBLK_REC, REC_THREADS, smem_bytes>>>(R, seq, h0, c0, P, out);
}